// round 14
// baseline (speedup 1.0000x reference)
#include <cuda_runtime.h>
#include <cuda_bf16.h>

// DiagPooling: x [B=8, C=128, H=512, W=512] fp32 -> out [B, 1, 513] fp32
// out[b, 0, o] = (1 / (128 * (512 - |o-256|))) * sum_{c,i} x[b, c, i, i + o - 256]
//
// FINAL — converged at the compulsory-traffic floor (verified over three
// identical reruns: kernel 126.8-126.9us = 843 MB at the measured ~6.65
// TB/s chip cap; totals 127.5/128.4/127.5us = launch-noise band).
// Falsified levers across 13 rounds: occupancy (R2), wave balance/LPT
// (R3/R8/R9), float4 vectorization x3 (R4/R5/R6), diagonal-walk DRAM
// locality (R7), MLP batch size (R11). Real wins: the R1 structure and
// single-launch zero-init fusion (R10, -2us).
//
// Structure: block = (row i via LPT width-descending permutation, batch
// b), 512 threads; thread t owns column j = j0 + t (coalesced). 128-
// channel register reduction (4 accumulators, unroll 8 -> 32 independent
// LDGs in flight), one pre-scaled atomicAdd into out[b*513 + (j-i+256)]
// (1.57M REDG over 4104 addresses, off the critical path).
//
// Fusion protocol: blocks bid 0..7 (first-wave, dependency-free) zero one
// batch of out[] each, __threadfence, signal g_zero_done. Every block
// runs its ~14us load loop FIRST, then thread0 spins until g_zero_done==8
// (satisfied ~10us earlier -> single poll; deadlock impossible),
// __syncthreads, then atomics. Last finished block resets both counters
// so every graph replay performs identical work (statics start at 0, so
// the first call is also correct). No early returns (syncthreads safety).

#define B_DIM 8
#define C_DIM 128
#define H_DIM 512
#define W_DIM 512
#define N_OFF 513
#define OUT_ELEMS (B_DIM * N_OFF)
#define NBLOCKS_TOTAL (H_DIM * B_DIM)   // 4096

__device__ int g_zero_done;        // zero-initialized at module load
__device__ int g_blocks_finished;  // zero-initialized at module load

__global__ __launch_bounds__(512) void diag_pool_kernel(
    const float* __restrict__ x, float* __restrict__ out)
{
    const int xblk = blockIdx.x;                 // 0..511
    const int b    = blockIdx.y;                 // 0..7
    const int t    = threadIdx.x;                // 0..511

    // ---- fused zero-init: first 8 blocks (bid 0..7) zero one batch each ----
    if (b == 0 && xblk < B_DIM) {
        float* dst = out + xblk * N_OFF;
        if (t < N_OFF) dst[t] = 0.0f;            // t covers 0..511
        if (t == 0) dst[512] = 0.0f;
        __syncthreads();                         // all zero stores issued
        if (t == 0) {
            __threadfence();                     // zeros visible at L2
            atomicAdd(&g_zero_done, 1);
        }
    }

    // ---- main work (LPT row order: widest rows first) ----
    const int d = 255 - (xblk >> 1);
    const int i = (xblk & 1) ? (511 - d) : d;

    const int j0 = (i - 256 > 0) ? (i - 256) : 0;
    const int j1 = (i + 256 < H_DIM - 1) ? (i + 256) : (H_DIM - 1);
    const int j = j0 + t;
    const bool active = (j <= j1);               // no early return (syncthreads below)

    float s = 0.0f;
    if (active) {
        const size_t ch_stride = (size_t)H_DIM * W_DIM;
        const float* p = x + ((size_t)b * C_DIM * H_DIM + (size_t)i) * W_DIM + j;

        float s0 = 0.f, s1 = 0.f, s2 = 0.f, s3 = 0.f;
        #pragma unroll 8
        for (int c = 0; c < C_DIM; c += 4) {
            s0 += __ldg(p + (size_t)(c + 0) * ch_stride);
            s1 += __ldg(p + (size_t)(c + 1) * ch_stride);
            s2 += __ldg(p + (size_t)(c + 2) * ch_stride);
            s3 += __ldg(p + (size_t)(c + 3) * ch_stride);
        }
        s = (s0 + s1) + (s2 + s3);
    }

    // ---- handshake: zeros must be in place before accumulation ----
    if (t == 0) {
        while (*(volatile int*)&g_zero_done < B_DIM) { /* spin (1 poll typ.) */ }
    }
    __syncthreads();

    if (active) {
        const int o = j - i + 256;               // diagonal id 0..512
        const int off = o - 256;
        const int dlen = H_DIM - (off < 0 ? -off : off);
        atomicAdd(&out[b * N_OFF + o], s / ((float)C_DIM * (float)dlen));
    }

    // ---- epoch reset so the next graph replay starts clean ----
    if (t == 0) {
        const int old = atomicAdd(&g_blocks_finished, 1);
        if (old == NBLOCKS_TOTAL - 1) {          // last block: all spins passed
            g_zero_done = 0;
            g_blocks_finished = 0;
            __threadfence();
        }
    }
}

extern "C" void kernel_launch(void* const* d_in, const int* in_sizes, int n_in,
                              void* d_out, int out_size) {
    const float* x = (const float*)d_in[0];
    float* out = (float*)d_out;

    dim3 grid(H_DIM, B_DIM);                     // 4096 blocks, one launch
    diag_pool_kernel<<<grid, 512>>>(x, out);
}

// round 15
// speedup vs baseline: 1.0078x; 1.0078x over previous
#include <cuda_runtime.h>
#include <cuda_bf16.h>

// DiagPooling: x [B=8, C=128, H=512, W=512] fp32 -> out [B, 1, 513] fp32
// out[b, 0, o] = (1 / (128 * (512 - |o-256|))) * sum_{c,i} x[b, c, i, i + o - 256]
//
// FINAL — converged at the compulsory-traffic floor, verified over FOUR
// identical reruns (kernel 126.8-127.4us; total 127.5-128.5us noise band).
// Floor model: 843 MB compulsory traffic (806 MB useful + ~4% unavoidable
// partial-sector edge waste) at the chip's measured path-independent LTS
// throughput cap (~6.64 TB/s sustained) = 127.0us. Falsified levers across
// 14 rounds: occupancy (R2), wave balance/LPT (R3/R8/R9), float4
// vectorization x3 (R4/R5/R6), diagonal-walk DRAM locality (R7), MLP batch
// size (R11). Real wins: the R1 structure and single-launch zero-init
// fusion (R10, -2us).
//
// Structure: block = (row i via LPT width-descending permutation, batch
// b), 512 threads; thread t owns column j = j0 + t (coalesced). 128-
// channel register reduction (4 accumulators, unroll 8 -> 32 independent
// LDGs in flight), one pre-scaled atomicAdd into out[b*513 + (j-i+256)]
// (1.57M REDG over 4104 addresses, off the critical path).
//
// Fusion protocol: blocks bid 0..7 (first-wave, dependency-free) zero one
// batch of out[] each, __threadfence, signal g_zero_done. Every block
// runs its ~14us load loop FIRST, then thread0 spins until g_zero_done==8
// (satisfied ~10us earlier -> single poll; deadlock impossible),
// __syncthreads, then atomics. Last finished block resets both counters
// so every graph replay performs identical work (statics start at 0, so
// the first call is also correct). No early returns (syncthreads safety).

#define B_DIM 8
#define C_DIM 128
#define H_DIM 512
#define W_DIM 512
#define N_OFF 513
#define OUT_ELEMS (B_DIM * N_OFF)
#define NBLOCKS_TOTAL (H_DIM * B_DIM)   // 4096

__device__ int g_zero_done;        // zero-initialized at module load
__device__ int g_blocks_finished;  // zero-initialized at module load

__global__ __launch_bounds__(512) void diag_pool_kernel(
    const float* __restrict__ x, float* __restrict__ out)
{
    const int xblk = blockIdx.x;                 // 0..511
    const int b    = blockIdx.y;                 // 0..7
    const int t    = threadIdx.x;                // 0..511

    // ---- fused zero-init: first 8 blocks (bid 0..7) zero one batch each ----
    if (b == 0 && xblk < B_DIM) {
        float* dst = out + xblk * N_OFF;
        if (t < N_OFF) dst[t] = 0.0f;            // t covers 0..511
        if (t == 0) dst[512] = 0.0f;
        __syncthreads();                         // all zero stores issued
        if (t == 0) {
            __threadfence();                     // zeros visible at L2
            atomicAdd(&g_zero_done, 1);
        }
    }

    // ---- main work (LPT row order: widest rows first) ----
    const int d = 255 - (xblk >> 1);
    const int i = (xblk & 1) ? (511 - d) : d;

    const int j0 = (i - 256 > 0) ? (i - 256) : 0;
    const int j1 = (i + 256 < H_DIM - 1) ? (i + 256) : (H_DIM - 1);
    const int j = j0 + t;
    const bool active = (j <= j1);               // no early return (syncthreads below)

    float s = 0.0f;
    if (active) {
        const size_t ch_stride = (size_t)H_DIM * W_DIM;
        const float* p = x + ((size_t)b * C_DIM * H_DIM + (size_t)i) * W_DIM + j;

        float s0 = 0.f, s1 = 0.f, s2 = 0.f, s3 = 0.f;
        #pragma unroll 8
        for (int c = 0; c < C_DIM; c += 4) {
            s0 += __ldg(p + (size_t)(c + 0) * ch_stride);
            s1 += __ldg(p + (size_t)(c + 1) * ch_stride);
            s2 += __ldg(p + (size_t)(c + 2) * ch_stride);
            s3 += __ldg(p + (size_t)(c + 3) * ch_stride);
        }
        s = (s0 + s1) + (s2 + s3);
    }

    // ---- handshake: zeros must be in place before accumulation ----
    if (t == 0) {
        while (*(volatile int*)&g_zero_done < B_DIM) { /* spin (1 poll typ.) */ }
    }
    __syncthreads();

    if (active) {
        const int o = j - i + 256;               // diagonal id 0..512
        const int off = o - 256;
        const int dlen = H_DIM - (off < 0 ? -off : off);
        atomicAdd(&out[b * N_OFF + o], s / ((float)C_DIM * (float)dlen));
    }

    // ---- epoch reset so the next graph replay starts clean ----
    if (t == 0) {
        const int old = atomicAdd(&g_blocks_finished, 1);
        if (old == NBLOCKS_TOTAL - 1) {          // last block: all spins passed
            g_zero_done = 0;
            g_blocks_finished = 0;
            __threadfence();
        }
    }
}

extern "C" void kernel_launch(void* const* d_in, const int* in_sizes, int n_in,
                              void* d_out, int out_size) {
    const float* x = (const float*)d_in[0];
    float* out = (float*)d_out;

    dim3 grid(H_DIM, B_DIM);                     // 4096 blocks, one launch
    diag_pool_kernel<<<grid, 512>>>(x, out);
}

// round 16
// speedup vs baseline: 1.0080x; 1.0003x over previous
#include <cuda_runtime.h>
#include <cuda_bf16.h>

// DiagPooling: x [B=8, C=128, H=512, W=512] fp32 -> out [B, 1, 513] fp32
// out[b, 0, o] = (1 / (128 * (512 - |o-256|))) * sum_{c,i} x[b, c, i, i + o - 256]
//
// FINAL — converged at the compulsory-traffic floor, verified over FIVE
// identical reruns (kernel 126.8-127.4us; total 127.5-128.5us noise band).
// Floor model: 843 MB compulsory traffic (806 MB useful + ~4% unavoidable
// partial-sector edge waste) at the chip's measured path-independent LTS
// throughput cap (~6.64 TB/s sustained) = 127.0us. Falsified levers across
// 15 rounds: occupancy (R2), wave balance/LPT (R3/R8/R9), float4
// vectorization x3 (R4/R5/R6), diagonal-walk DRAM locality (R7), MLP batch
// size (R11). Real wins: the R1 structure and single-launch zero-init
// fusion (R10, -2us).
//
// Structure: block = (row i via LPT width-descending permutation, batch
// b), 512 threads; thread t owns column j = j0 + t (coalesced). 128-
// channel register reduction (4 accumulators, unroll 8 -> 32 independent
// LDGs in flight), one pre-scaled atomicAdd into out[b*513 + (j-i+256)]
// (1.57M REDG over 4104 addresses, off the critical path).
//
// Fusion protocol: blocks bid 0..7 (first-wave, dependency-free) zero one
// batch of out[] each, __threadfence, signal g_zero_done. Every block
// runs its ~14us load loop FIRST, then thread0 spins until g_zero_done==8
// (satisfied ~10us earlier -> single poll; deadlock impossible),
// __syncthreads, then atomics. Last finished block resets both counters
// so every graph replay performs identical work (statics start at 0, so
// the first call is also correct). No early returns (syncthreads safety).

#define B_DIM 8
#define C_DIM 128
#define H_DIM 512
#define W_DIM 512
#define N_OFF 513
#define OUT_ELEMS (B_DIM * N_OFF)
#define NBLOCKS_TOTAL (H_DIM * B_DIM)   // 4096

__device__ int g_zero_done;        // zero-initialized at module load
__device__ int g_blocks_finished;  // zero-initialized at module load

__global__ __launch_bounds__(512) void diag_pool_kernel(
    const float* __restrict__ x, float* __restrict__ out)
{
    const int xblk = blockIdx.x;                 // 0..511
    const int b    = blockIdx.y;                 // 0..7
    const int t    = threadIdx.x;                // 0..511

    // ---- fused zero-init: first 8 blocks (bid 0..7) zero one batch each ----
    if (b == 0 && xblk < B_DIM) {
        float* dst = out + xblk * N_OFF;
        if (t < N_OFF) dst[t] = 0.0f;            // t covers 0..511
        if (t == 0) dst[512] = 0.0f;
        __syncthreads();                         // all zero stores issued
        if (t == 0) {
            __threadfence();                     // zeros visible at L2
            atomicAdd(&g_zero_done, 1);
        }
    }

    // ---- main work (LPT row order: widest rows first) ----
    const int d = 255 - (xblk >> 1);
    const int i = (xblk & 1) ? (511 - d) : d;

    const int j0 = (i - 256 > 0) ? (i - 256) : 0;
    const int j1 = (i + 256 < H_DIM - 1) ? (i + 256) : (H_DIM - 1);
    const int j = j0 + t;
    const bool active = (j <= j1);               // no early return (syncthreads below)

    float s = 0.0f;
    if (active) {
        const size_t ch_stride = (size_t)H_DIM * W_DIM;
        const float* p = x + ((size_t)b * C_DIM * H_DIM + (size_t)i) * W_DIM + j;

        float s0 = 0.f, s1 = 0.f, s2 = 0.f, s3 = 0.f;
        #pragma unroll 8
        for (int c = 0; c < C_DIM; c += 4) {
            s0 += __ldg(p + (size_t)(c + 0) * ch_stride);
            s1 += __ldg(p + (size_t)(c + 1) * ch_stride);
            s2 += __ldg(p + (size_t)(c + 2) * ch_stride);
            s3 += __ldg(p + (size_t)(c + 3) * ch_stride);
        }
        s = (s0 + s1) + (s2 + s3);
    }

    // ---- handshake: zeros must be in place before accumulation ----
    if (t == 0) {
        while (*(volatile int*)&g_zero_done < B_DIM) { /* spin (1 poll typ.) */ }
    }
    __syncthreads();

    if (active) {
        const int o = j - i + 256;               // diagonal id 0..512
        const int off = o - 256;
        const int dlen = H_DIM - (off < 0 ? -off : off);
        atomicAdd(&out[b * N_OFF + o], s / ((float)C_DIM * (float)dlen));
    }

    // ---- epoch reset so the next graph replay starts clean ----
    if (t == 0) {
        const int old = atomicAdd(&g_blocks_finished, 1);
        if (old == NBLOCKS_TOTAL - 1) {          // last block: all spins passed
            g_zero_done = 0;
            g_blocks_finished = 0;
            __threadfence();
        }
    }
}

extern "C" void kernel_launch(void* const* d_in, const int* in_sizes, int n_in,
                              void* d_out, int out_size) {
    const float* x = (const float*)d_in[0];
    float* out = (float*)d_out;

    dim3 grid(H_DIM, B_DIM);                     // 4096 blocks, one launch
    diag_pool_kernel<<<grid, 512>>>(x, out);
}